// round 17
// baseline (speedup 1.0000x reference)
#include <cuda_runtime.h>
#include <math.h>
#include <stdint.h>

// Problem constants
#define BB   128
#define NN   256
#define DIN  128
#define HH   8
#define DK   16
#define HK   128
#define ROWS (BB*NN)        // 32768
#define NORMC 0.25f
#define SPS  257            // score/prob row stride (odd => conflict-free)
#define RST  20             // red row stride (mult of 4 => 16B-aligned rows)

typedef unsigned long long u64;

// ---- f32x2 packed math ----
__device__ __forceinline__ u64 pack2(float a, float b) {
    u64 r; asm("mov.b64 %0, {%1, %2};" : "=l"(r) : "f"(a), "f"(b)); return r;
}
__device__ __forceinline__ u64 fma2(u64 a, u64 b, u64 c) {
    u64 d; asm("fma.rn.f32x2 %0, %1, %2, %3;" : "=l"(d) : "l"(a), "l"(b), "l"(c)); return d;
}
__device__ __forceinline__ u64 addp2(u64 a, u64 b) {
    u64 d; asm("add.rn.f32x2 %0, %1, %2;" : "=l"(d) : "l"(a), "l"(b)); return d;
}
__device__ __forceinline__ float2 unpack2(u64 v) {
    float2 f; asm("mov.b64 {%0, %1}, %2;" : "=f"(f.x), "=f"(f.y) : "l"(v)); return f;
}

// ---------------- device-global scratch ----------------
// Q/K/V head-major: [h][b*N+n][16]
__device__ float g_Q[(size_t)HH * ROWS * DK];
__device__ float g_K[(size_t)HH * ROWS * DK];
__device__ float g_V[(size_t)HH * ROWS * DK];
__device__ float g_heads[(size_t)ROWS * HK];

__device__ float g_breaks[512];
__device__ float g_tab[512 * 16];
__device__ float2 g_es[(size_t)BB * NN * NN];   // {e, bits(seg|mask<<15)} 64MB

// =====================================================================
// PWL build (one block, 512 threads)
// =====================================================================
__global__ void pwl_build_kernel(const float* __restrict__ mw1, const float* __restrict__ mb1,
                                 const float* __restrict__ mw2, const float* __restrict__ mb2,
                                 const float* __restrict__ mw3, const float* __restrict__ mb3)
{
    __shared__ float w1[16], b1[16], w2[256], b2[16], w3[128], b3[8];
    __shared__ float tsort[16];
    __shared__ float cand[512];
    __shared__ int   cnt;

    const int tid = threadIdx.x;
    if (tid < 16)  { w1[tid] = mw1[tid]; b1[tid] = mb1[tid]; b2[tid] = mb2[tid]; }
    if (tid < 256) w2[tid] = mw2[tid];
    if (tid < 128) w3[tid] = mw3[tid];
    if (tid < 8)   b3[tid] = mb3[tid];
    cand[tid] = 3.0e38f;
    if (tid == 0) cnt = 16;
    __syncthreads();

    if (tid < 16) {
        float t = (w1[tid] != 0.f) ? (-b1[tid] / w1[tid]) : 3.0e38f;
        cand[tid] = t;
    }
    __syncthreads();
    if (tid == 0) {
        for (int i = 0; i < 16; i++) tsort[i] = cand[i];
        for (int i = 1; i < 16; i++) {
            float v = tsort[i]; int k = i - 1;
            while (k >= 0 && tsort[k] > v) { tsort[k + 1] = tsort[k]; k--; }
            tsort[k + 1] = v;
        }
    }
    __syncthreads();

    if (tid < 17 * 16) {
        int iv = tid >> 4, c = tid & 15;
        float lo = (iv == 0)  ? -3.0e38f : tsort[iv - 1];
        float hi = (iv == 16) ?  3.0e38f : tsort[iv];
        if (lo < hi) {
            float m;
            if (lo <= -1e30f && hi >= 1e30f) m = 0.f;
            else if (lo <= -1e30f)           m = hi - 1.f;
            else if (hi >=  1e30f)           m = lo + 1.f;
            else                             m = 0.5f * (lo + hi);
            float g = 0.f, q = b2[c];
            for (int n = 0; n < 16; n++) {
                if (fmaf(m, w1[n], b1[n]) > 0.f) {
                    g = fmaf(w1[n], w2[n * 16 + c], g);
                    q = fmaf(b1[n], w2[n * 16 + c], q);
                }
            }
            if (g != 0.f) {
                float x = -q / g;
                if (x > lo && x < hi && fabsf(x) < 1e30f) {
                    int k = atomicAdd(&cnt, 1);
                    cand[k] = x;
                }
            }
        }
    }
    __syncthreads();
    const int ncand = cnt;

    for (int k = 2; k <= 512; k <<= 1) {
        for (int j = k >> 1; j > 0; j >>= 1) {
            int ixj = tid ^ j;
            if (ixj > tid) {
                bool up = (tid & k) == 0;
                float a = cand[tid], b = cand[ixj];
                if ((a > b) == up) { cand[tid] = b; cand[ixj] = a; }
            }
            __syncthreads();
        }
    }

    g_breaks[tid] = (tid < ncand) ? cand[tid] : 3.0e38f;

    if (tid <= ncand) {
        float lo = (tid == 0)     ? -3.0e38f : cand[tid - 1];
        float hi = (tid == ncand) ?  3.0e38f : cand[tid];
        float m;
        if (lo <= -1e30f && hi >= 1e30f) m = 0.f;
        else if (lo <= -1e30f)           m = hi - 1.f;
        else if (hi >=  1e30f)           m = lo + 1.f;
        else                             m = 0.5f * (lo + hi);

        float slope[8], inter[8];
        for (int h = 0; h < 8; h++) { slope[h] = 0.f; inter[h] = b3[h]; }
        for (int c = 0; c < 16; c++) {
            float gc = 0.f, qc = b2[c];
            for (int n = 0; n < 16; n++) {
                if (fmaf(m, w1[n], b1[n]) > 0.f) {
                    gc = fmaf(w1[n], w2[n * 16 + c], gc);
                    qc = fmaf(b1[n], w2[n * 16 + c], qc);
                }
            }
            if (fmaf(gc, m, qc) > 0.f) {
                for (int h = 0; h < 8; h++) {
                    slope[h] = fmaf(gc, w3[c * 8 + h], slope[h]);
                    inter[h] = fmaf(qc, w3[c * 8 + h], inter[h]);
                }
            }
        }
        for (int h = 0; h < 8; h++) {
            g_tab[tid * 16 + h * 2]     = slope[h];
            g_tab[tid * 16 + h * 2 + 1] = inter[h];
        }
    }
}

// =====================================================================
// GEMM body (QKV): 128 rows/block, 8 rows/thread; full 128-col W in smem.
// =====================================================================
__device__ __forceinline__ void gemm_body(const float* __restrict__ A,
                                          const float* __restrict__ Wraw,
                                          float* __restrict__ Out,
                                          int row0)
{
    extern __shared__ float sm[];
    float* Wsm = sm;   // [128][128]

    const int tid = threadIdx.x;

    for (int i4 = tid; i4 < 4096; i4 += 256) {
        int d = i4 >> 5, c4 = (i4 & 31) * 4;
        float4 w = *(const float4*)(Wraw + (c4 >> 4) * (DIN * 16) + d * 16 + (c4 & 15));
        *(float4*)(Wsm + d * 128 + c4) = w;
    }
    __syncthreads();

    const int tx = tid & 15, ty = tid >> 4;
    const int ca = tx * 4;
    const int r0 = ty * 8;

    const float* Ab = A + (size_t)(row0 + r0) * 128;

    u64 acc2[8][4];
#pragma unroll
    for (int u = 0; u < 8; u++)
#pragma unroll
        for (int k = 0; k < 4; k++) acc2[u][k] = 0ull;

    for (int dc = 0; dc < 128; dc += 4) {
        float4 a4[8];
#pragma unroll
        for (int u = 0; u < 8; u++) a4[u] = *(const float4*)(Ab + (size_t)u * 128 + dc);
#pragma unroll
        for (int dd = 0; dd < 4; dd++) {
            ulonglong2 w0 = *(const ulonglong2*)(Wsm + (dc + dd) * 128 + ca);
            ulonglong2 w1 = *(const ulonglong2*)(Wsm + (dc + dd) * 128 + 64 + ca);
#pragma unroll
            for (int u = 0; u < 8; u++) {
                float a = (dd == 0) ? a4[u].x : (dd == 1) ? a4[u].y : (dd == 2) ? a4[u].z : a4[u].w;
                u64 a2 = pack2(a, a);
                acc2[u][0] = fma2(a2, w0.x, acc2[u][0]);
                acc2[u][1] = fma2(a2, w0.y, acc2[u][1]);
                acc2[u][2] = fma2(a2, w1.x, acc2[u][2]);
                acc2[u][3] = fma2(a2, w1.y, acc2[u][3]);
            }
        }
    }
#pragma unroll
    for (int u = 0; u < 8; u++) {
        float2 p0 = unpack2(acc2[u][0]), p1 = unpack2(acc2[u][1]);
        float2 p2 = unpack2(acc2[u][2]), p3 = unpack2(acc2[u][3]);
        float4 o0 = {p0.x, p0.y, p1.x, p1.y};
        float4 o1 = {p2.x, p2.y, p3.x, p3.y};
        const int row = row0 + r0 + u;
        int h0 = ca >> 4, h1 = (64 + ca) >> 4;
        *(float4*)(Out + ((size_t)h0 * ROWS + row) * 16 + (ca & 15)) = o0;
        *(float4*)(Out + ((size_t)h1 * ROWS + row) * 16 + (ca & 15)) = o1;
    }
}

// =====================================================================
// gemm_qkv + es fused launch: z<3 = QKV projections (128 rows/block);
// z==3 = (e,seg) pack pass (DRAM-bound, overlaps the FMA-bound gemms)
// =====================================================================
__global__ void __launch_bounds__(256, 2) gemm_qkv_seg_kernel(const float* __restrict__ q,
                                                              const float* __restrict__ hx,
                                                              const float* __restrict__ Wq,
                                                              const float* __restrict__ Wk,
                                                              const float* __restrict__ Wv,
                                                              const float* __restrict__ Ebm,
                                                              const int* __restrict__ mask)
{
    const int z = blockIdx.y;
    if (z == 3) {
        extern __shared__ float smf[];
        float* sB = smf;
        const int tid = threadIdx.x;
        for (int i = tid; i < 512; i += 256) sB[i] = g_breaks[i];
        __syncthreads();
        const size_t stride = 256 * 256;   // 256 blocks x 256 threads
        size_t base = (size_t)blockIdx.x * 256 + tid;
#pragma unroll 2
        for (int it = 0; it < 32; it++) {
            size_t v = base + (size_t)it * stride;   // float4 cell index
            float4 e4 = ((const float4*)Ebm)[v];
            int4   m4 = ((const int4*)mask)[v];
            const float ev[4] = {e4.x, e4.y, e4.z, e4.w};
            const int   mv[4] = {m4.x, m4.y, m4.z, m4.w};
            float sv[4];
#pragma unroll
            for (int p = 0; p < 4; p++) {
                float e = ev[p];
                int seg = 0;
#pragma unroll
                for (int st = 256; st >= 1; st >>= 1) {
                    int cnd = seg + st;
                    if (e >= sB[cnd - 1]) seg = cnd;
                }
                sv[p] = __int_as_float(seg | (mv[p] ? 0x8000 : 0));
            }
            float4* dst = (float4*)g_es + v * 2;
            dst[0] = make_float4(ev[0], sv[0], ev[1], sv[1]);
            dst[1] = make_float4(ev[2], sv[2], ev[3], sv[3]);
        }
        return;
    }
    const float* A = (z == 0) ? q : hx;
    const float* W = (z == 0) ? Wq : (z == 1) ? Wk : Wv;
    float* Out = (z == 0) ? g_Q : (z == 1) ? g_K : g_V;
    gemm_body(A, W, Out, blockIdx.x * 128);
}

// =====================================================================
// gemm_out: column-halved (grid.y = half). W tile 128x64 = 32KB; 3 blk/SM.
// =====================================================================
__global__ void __launch_bounds__(256, 3) gemm_out_kernel(const float* __restrict__ Wo,
                                                          float* __restrict__ Out)
{
    extern __shared__ float sm[];
    float* Wsm = sm;   // [128][64]

    const int tid = threadIdx.x;
    const int ch  = blockIdx.y;          // column half 0/1
    const int row0 = blockIdx.x * 128;

    for (int i4 = tid; i4 < 2048; i4 += 256) {
        int d = i4 >> 4, c4 = (i4 & 15) * 4;
        *(float4*)(Wsm + d * 64 + c4) = *(const float4*)(Wo + d * 128 + ch * 64 + c4);
    }
    __syncthreads();

    const int tx = tid & 15, ty = tid >> 4;
    const int ca = tx * 4;
    const int r0 = ty * 8;

    const float* Ab = g_heads + (size_t)(row0 + r0) * 128;

    u64 acc2[8][2];
#pragma unroll
    for (int u = 0; u < 8; u++) { acc2[u][0] = 0ull; acc2[u][1] = 0ull; }

    for (int dc = 0; dc < 128; dc += 4) {
        float4 a4[8];
#pragma unroll
        for (int u = 0; u < 8; u++) a4[u] = *(const float4*)(Ab + (size_t)u * 128 + dc);
#pragma unroll
        for (int dd = 0; dd < 4; dd++) {
            ulonglong2 w0 = *(const ulonglong2*)(Wsm + (dc + dd) * 64 + ca);
#pragma unroll
            for (int u = 0; u < 8; u++) {
                float a = (dd == 0) ? a4[u].x : (dd == 1) ? a4[u].y : (dd == 2) ? a4[u].z : a4[u].w;
                u64 a2 = pack2(a, a);
                acc2[u][0] = fma2(a2, w0.x, acc2[u][0]);
                acc2[u][1] = fma2(a2, w0.y, acc2[u][1]);
            }
        }
    }
#pragma unroll
    for (int u = 0; u < 8; u++) {
        float2 p0 = unpack2(acc2[u][0]), p1 = unpack2(acc2[u][1]);
        float4 o0 = {p0.x, p0.y, p1.x, p1.y};
        const int row = row0 + r0 + u;
        *(float4*)(Out + (size_t)row * 128 + ch * 64 + ca) = o0;
    }
}

// =====================================================================
// Fused attention v11: v10 + swizzled red (4-phase P3 stores).
// Block = (b, 64-row region, head). 512 threads, 2 blocks/SM.
// =====================================================================
__global__ void __launch_bounds__(512, 2)
attn_fused_kernel()
{
    extern __shared__ float sm[];
    float* SP   = sm;                 // [32][257]
    float* red  = SP + 8224;          // [16][32][20] (col swizzled)
    float* sV   = red + 10240;        // [256][16]
    float* Qsm  = sV + 4096;          // [32][16]
    float* sT   = Qsm + 512;          // [304][2]
    float* sInv = sT + 608;           // [32]

    const int tid    = threadIdx.x;
    const int b      = blockIdx.y;
    const int itile0 = (blockIdx.x & 3) * 64;
    const int head   = blockIdx.x >> 2;

    const size_t hbase = (size_t)head * ROWS + (size_t)b * NN;

    const int warp = tid >> 5, lane = tid & 31;
    const int jq8 = warp & 7;
    const int jgl = jq8 * 32 + lane;
    const int rh  = warp >> 3;

    u64 K2[8];
    {
        const ulonglong2* Kg = (const ulonglong2*)(g_K + (hbase + jgl) * 16);
#pragma unroll
        for (int qq = 0; qq < 4; qq++) {
            ulonglong2 kv = Kg[qq];
            K2[qq * 2]     = kv.x;
            K2[qq * 2 + 1] = kv.y;
        }
    }

    {
        const float4* Vg = (const float4*)(g_V + hbase * 16);
#pragma unroll
        for (int p = 0; p < 2; p++) {
            int q4 = tid + 512 * p;
            *(float4*)(sV + q4 * 4) = Vg[q4];
        }
        if (tid < 304) {
            sT[tid * 2]     = g_tab[tid * 16 + head * 2];
            sT[tid * 2 + 1] = g_tab[tid * 16 + head * 2 + 1];
        }
    }

    for (int tile = 0; tile < 2; tile++) {
        const int itile = itile0 + tile * 32;

        __syncthreads();
        if (tid < 128) {
            float4 qv = *(const float4*)(g_Q + (hbase + itile) * 16 + tid * 4);
            qv.x *= NORMC; qv.y *= NORMC; qv.z *= NORMC; qv.w *= NORMC;
            *(float4*)(Qsm + tid * 4) = qv;
        }
        __syncthreads();

        // ---- P1: SP = bias(e) + Q.K  (single (e,seg) LDG.64 per row)
        {
            const float2* esp = g_es + (size_t)(b * NN + itile) * NN + jgl;
            const int rbase = rh * 16;

            float2 es_nxt = esp[(size_t)rbase * NN];

#pragma unroll 4
            for (int rr = 0; rr < 16; rr++) {
                const int r = rbase + rr;
                float2 es_cur = es_nxt;
                if (rr < 15) es_nxt = esp[(size_t)(r + 1) * NN];

                const ulonglong2* qp = (const ulonglong2*)(Qsm + r * 16);
                ulonglong2 qa = qp[0], qb = qp[1], qc = qp[2], qd = qp[3];
                u64 d2 = 0ull;
                d2 = fma2(qa.x, K2[0], d2); d2 = fma2(qa.y, K2[1], d2);
                d2 = fma2(qb.x, K2[2], d2); d2 = fma2(qb.y, K2[3], d2);
                d2 = fma2(qc.x, K2[4], d2); d2 = fma2(qc.y, K2[5], d2);
                d2 = fma2(qd.x, K2[6], d2); d2 = fma2(qd.y, K2[7], d2);
                float2 df = unpack2(d2);
                float d = df.x + df.y;

                unsigned int sbits = __float_as_uint(es_cur.y);
                int seg = sbits & 0x7fff;
                float2 t = *(const float2*)(sT + seg * 2);
                float bias = (sbits & 0x8000) ? -INFINITY : fmaf(t.x, es_cur.x, t.y);
                SP[r * SPS + jgl] = bias + d;
            }
        }
        __syncthreads();

        // ---- P2: softmax (unnormalized exp; inv per row)
        {
#pragma unroll
            for (int rr = 0; rr < 2; rr++) {
                const int r = warp * 2 + rr;
                float v[8];
#pragma unroll
                for (int m = 0; m < 8; m++) v[m] = SP[r * SPS + lane + 32 * m];
                float mx = v[0];
#pragma unroll
                for (int m = 1; m < 8; m++) mx = fmaxf(mx, v[m]);
#pragma unroll
                for (int o = 16; o > 0; o >>= 1) mx = fmaxf(mx, __shfl_xor_sync(0xffffffffu, mx, o));
                float s = 0.f;
#pragma unroll
                for (int m = 0; m < 8; m++) { v[m] = __expf(v[m] - mx); s += v[m]; }
#pragma unroll
                for (int o = 16; o > 0; o >>= 1) s += __shfl_xor_sync(0xffffffffu, s, o);
                if (lane == 0) sInv[r] = 1.f / s;
#pragma unroll
                for (int m = 0; m < 8; m++) SP[r * SPS + lane + 32 * m] = v[m];
            }
        }
        __syncthreads();

        // ---- P3: AV, (2-row, 8-v) lanes; swizzled red stores (4-phase)
        {
            const int j0 = warp * 16;
            const int r2 = (lane & 15) * 2;
            const int v0 = (lane >> 4) * 8;
            const int sw = ((r2 >> 1) & 1) * 4;   // row-pair swizzle
            u64 acc[8];
#pragma unroll
            for (int v = 0; v < 8; v++) acc[v] = 0ull;
#pragma unroll
            for (int jj = 0; jj < 16; jj++) {
                const int j = j0 + jj;
                float pa = SP[r2 * SPS + j];
                float pb = SP[(r2 + 1) * SPS + j];
                u64 pa2 = pack2(pa, pa);
                u64 pb2 = pack2(pb, pb);
                const ulonglong2* vp = (const ulonglong2*)(sV + j * 16 + v0);
                ulonglong2 va = vp[0], vb = vp[1];
                acc[0] = fma2(pa2, va.x, acc[0]); acc[1] = fma2(pa2, va.y, acc[1]);
                acc[2] = fma2(pa2, vb.x, acc[2]); acc[3] = fma2(pa2, vb.y, acc[3]);
                acc[4] = fma2(pb2, va.x, acc[4]); acc[5] = fma2(pb2, va.y, acc[5]);
                acc[6] = fma2(pb2, vb.x, acc[6]); acc[7] = fma2(pb2, vb.y, acc[7]);
            }
            ulonglong2* rpa = (ulonglong2*)(red + (warp * 32 + r2) * RST + v0 + sw);
            ulonglong2* rpb = (ulonglong2*)(red + (warp * 32 + r2 + 1) * RST + v0 + sw);
            rpa[0] = make_ulonglong2(acc[0], acc[1]);
            rpa[1] = make_ulonglong2(acc[2], acc[3]);
            rpb[0] = make_ulonglong2(acc[4], acc[5]);
            rpb[1] = make_ulonglong2(acc[6], acc[7]);
        }
        __syncthreads();

        // ---- P4: sum 16 j-group partials (packed, matching swizzle)
        if (tid < 256) {
            const int r = tid >> 3, vp = tid & 7;
            const int sw = ((r >> 1) & 1) * 4;
            u64 s = 0ull;
#pragma unroll
            for (int jq = 0; jq < 16; jq++)
                s = addp2(s, *(const u64*)(red + (jq * 32 + r) * RST + vp * 2 + sw));
            float inv = sInv[r];
            float2 f = unpack2(s);
            f.x *= inv; f.y *= inv;
            *(float2*)(g_heads + (size_t)(b * NN + itile + r) * HK + head * 16 + vp * 2) = f;
        }
    }
}

// =====================================================================
// host launcher
// =====================================================================
extern "C" void kernel_launch(void* const* d_in, const int* in_sizes, int n_in,
                              void* d_out, int out_size)
{
    (void)in_sizes; (void)n_in; (void)out_size;
    const float* q    = (const float*)d_in[0];
    const float* hx   = (const float*)d_in[1];
    const int*   mask = (const int*)d_in[2];
    const float* edge = (const float*)d_in[3];
    const float* Wq   = (const float*)d_in[4];
    const float* Wk   = (const float*)d_in[5];
    const float* Wv   = (const float*)d_in[6];
    const float* Wo   = (const float*)d_in[7];
    const float* mw1  = (const float*)d_in[8];
    const float* mb1  = (const float*)d_in[9];
    const float* mw2  = (const float*)d_in[10];
    const float* mb2  = (const float*)d_in[11];
    const float* mw3  = (const float*)d_in[12];
    const float* mb3  = (const float*)d_in[13];

    const int smem_qkv  = 128 * 128 * 4;   // 65,536 B
    const int smem_out  = 128 * 64 * 4;    // 32,768 B -> 3 blocks/SM
    const int smem_attn = 23712 * 4;       // 94,848 B -> 2 blocks/SM

    cudaFuncSetAttribute(gemm_qkv_seg_kernel, cudaFuncAttributeMaxDynamicSharedMemorySize, smem_qkv);
    cudaFuncSetAttribute(gemm_out_kernel,     cudaFuncAttributeMaxDynamicSharedMemorySize, smem_out);
    cudaFuncSetAttribute(attn_fused_kernel,   cudaFuncAttributeMaxDynamicSharedMemorySize, smem_attn);

    pwl_build_kernel<<<1, 512>>>(mw1, mb1, mw2, mb2, mw3, mb3);

    // QKV projections (128 rows/block) + (e,seg) pack in one launch
    gemm_qkv_seg_kernel<<<dim3(ROWS / 128, 4), 256, smem_qkv>>>(q, hx, Wq, Wk, Wv, edge, mask);

    attn_fused_kernel<<<dim3(32, BB), 512, smem_attn>>>();

    // output projection, column-halved for wave balance (512 blocks @ 3/SM)
    gemm_out_kernel<<<dim3(ROWS / 128, 2), 256, smem_out>>>(Wo, (float*)d_out);
}